// round 3
// baseline (speedup 1.0000x reference)
#include <cuda_runtime.h>
#include <cstdint>

#define TDIM 1024
#define HDIM 2048
#define IDIM 5632
#define NEXP 8
#define TOPK 2
#define NROWS (TDIM * TOPK)       // 2048 routed rows
#define N1 (2 * IDIM)             // 11264 (gate+up)
#define BM 128
#define BN 128
#define BK 32                     // 32 floats = 128 bytes = one SW128 atom row
#define MAXTILES 24

// ---------------- scratch (device globals: no allocations allowed) ----------
__device__ int   g_row_token[NROWS];
__device__ float g_row_weight[NROWS];
__device__ int   g_row_slot[NROWS];
__device__ int   g_tile_expert[MAXTILES];
__device__ int   g_tile_rowstart[MAXTILES];
__device__ int   g_tile_rowcnt[MAXTILES];
__device__ int   g_ntiles;
__device__ float g_h13[(size_t)NROWS * N1];       // 88 MB
__device__ float g_act[(size_t)NROWS * IDIM];     // 44 MB (pre-rounded to tf32)
__device__ float g_partial[(size_t)NROWS * HDIM]; // 16 MB

// ---------------- routing ---------------------------------------------------
__global__ void route_kernel(const int* __restrict__ ids, const float* __restrict__ w)
{
    __shared__ int cnt[NEXP];
    __shared__ int off[NEXP];
    __shared__ int cur[NEXP];
    int tid = threadIdx.x;
    if (tid < NEXP) cnt[tid] = 0;
    __syncthreads();
    for (int a = tid; a < NROWS; a += blockDim.x)
        atomicAdd(&cnt[ids[a]], 1);
    __syncthreads();
    if (tid == 0) {
        int s = 0;
        for (int e = 0; e < NEXP; e++) { off[e] = s; cur[e] = s; s += cnt[e]; }
        int nt = 0;
        for (int e = 0; e < NEXP; e++) {
            for (int r = 0; r < cnt[e]; r += BM) {
                g_tile_expert[nt]   = e;
                g_tile_rowstart[nt] = off[e] + r;
                g_tile_rowcnt[nt]   = min(BM, cnt[e] - r);
                nt++;
            }
        }
        g_ntiles = nt;
    }
    __syncthreads();
    for (int a = tid; a < NROWS; a += blockDim.x) {
        int e = ids[a];
        int pos = atomicAdd(&cur[e], 1);
        g_row_token[pos]  = a / TOPK;
        g_row_weight[pos] = w[a];
        g_row_slot[pos]   = a;      // t*TOPK + k
    }
}

// ---------------- helpers ----------------------------------------------------
__device__ __forceinline__ uint32_t smem_u32(const void* p)
{
    uint32_t a;
    asm("{ .reg .u64 t; cvta.to.shared.u64 t, %1; cvt.u32.u64 %0, t; }"
        : "=r"(a) : "l"(p));
    return a;
}

__device__ __forceinline__ uint32_t f2tf32(float x)
{
    uint32_t r;
    asm("cvt.rna.tf32.f32 %0, %1;" : "=r"(r) : "f"(x));
    return r;
}

#define SWZ128(x) ((x) ^ (((x) >> 3) & 0x70))

__device__ __forceinline__ void ldsm_x4(uint32_t& r0, uint32_t& r1,
                                        uint32_t& r2, uint32_t& r3, uint32_t addr)
{
    asm volatile("ldmatrix.sync.aligned.m8n8.x4.shared.b16 {%0,%1,%2,%3}, [%4];"
                 : "=r"(r0), "=r"(r1), "=r"(r2), "=r"(r3) : "r"(addr));
}

__device__ __forceinline__ void mma_tf32(float (&d)[4],
                                         const uint32_t (&a)[4],
                                         const uint32_t (&b)[2])
{
    asm volatile(
        "mma.sync.aligned.m16n8k8.row.col.f32.tf32.tf32.f32 "
        "{%0,%1,%2,%3}, {%4,%5,%6,%7}, {%8,%9}, {%0,%1,%2,%3};\n"
        : "+f"(d[0]), "+f"(d[1]), "+f"(d[2]), "+f"(d[3])
        : "r"(a[0]), "r"(a[1]), "r"(a[2]), "r"(a[3]),
          "r"(b[0]), "r"(b[1]));
}

// ---------------- grouped GEMM (mma.sync tf32 + ldmatrix, 128x128x32) -------
// G2=false: h13[r, n] = sum_h hidden[token[r], h] * w13[e, n, h]
// G2=true : partial[slot[r], n] = w[r] * sum_i act[r, i] * w2[e, n, i]
// SMEM (dyn, 1024-aligned): A0[16K] B0[16K] A1[16K] B1[16K]; SW128, 128B rows.
template<int KDIM, int NTOT, bool G2>
__global__ void __launch_bounds__(256, 2)
moe_gemm_ldsm(const float* __restrict__ Asrc, const float* __restrict__ Bsrc)
{
    const int tile = blockIdx.x;
    if (tile >= g_ntiles) return;
    const int e        = g_tile_expert[tile];
    const int rowstart = g_tile_rowstart[tile];
    const int rowcnt   = g_tile_rowcnt[tile];
    const int nbase    = blockIdx.y * BN;

    extern __shared__ uint32_t dsm[];
    const uint32_t smbase = smem_u32(dsm);
    const uint32_t base   = (smbase + 1023u) & ~1023u;
    char* dynb            = (char*)dsm + (base - smbase);
    const uint32_t aAddr[2] = { base,         base + 32768 };
    const uint32_t bAddr[2] = { base + 16384, base + 49152 };
    const uint32_t aOff[2]  = { 0u,     32768u };
    const uint32_t bOff[2]  = { 16384u, 49152u };

    const int tid  = threadIdx.x;
    const int lane = tid & 31;
    const int warp = tid >> 5;
    const int wm   = (warp & 1) * 64;
    const int wn   = (warp >> 1) * 32;

    // --- staging plan: 1024 float4 slots each for A and B (4 per thread) ----
    const float* Aext = G2 ? (const float*)g_act : Asrc;
    const float* Bexp = Bsrc + (size_t)e * NTOT * KDIM;
    const float* aSrc[4]; uint32_t aDst[4];
    const float* bSrc[4]; uint32_t bDst[4];
#pragma unroll
    for (int i = 0; i < 4; i++) {
        int slot = tid + 256 * i;
        int row = slot >> 3, grp = slot & 7;
        int re = row < rowcnt ? row : rowcnt - 1;
        size_t srow = G2 ? (size_t)(rowstart + re)
                         : (size_t)g_row_token[rowstart + re];
        aSrc[i] = Aext + srow * KDIM + grp * 4;
        aDst[i] = SWZ128((uint32_t)(row * 128 + grp * 16));
        bSrc[i] = Bexp + (size_t)(nbase + row) * KDIM + grp * 4;
        bDst[i] = aDst[i];
    }

    // --- ldmatrix per-lane address components --------------------------------
    const int arow = wm + (lane & 15);
    const int ahh  = lane >> 4;
    const uint32_t aswz = (uint32_t)(arow & 7) << 4;
    const int brow = wn + ((lane >> 4) << 3) + (lane & 7);
    const int bhh  = (lane >> 3) & 1;
    const uint32_t bswz = (uint32_t)(brow & 7) << 4;
    uint32_t aCol[4], bCol[4];
#pragma unroll
    for (int ks = 0; ks < 4; ks++) {
        aCol[ks] = ((uint32_t)(ks * 32 + ahh * 16)) ^ aswz;
        bCol[ks] = ((uint32_t)(ks * 32 + bhh * 16)) ^ bswz;
    }
    const uint32_t aRowOff = (uint32_t)arow * 128;
    const uint32_t bRowOff = (uint32_t)brow * 128;

    float acc[4][4][4];
#pragma unroll
    for (int mt = 0; mt < 4; mt++)
#pragma unroll
        for (int nt = 0; nt < 4; nt++)
#pragma unroll
            for (int i = 0; i < 4; i++) acc[mt][nt][i] = 0.f;

    const int KITER = KDIM / BK;
    float4 aR[4], bR[4];

    // prologue: stage k-tile 0 into buf 0
#pragma unroll
    for (int i = 0; i < 4; i++) { aR[i] = *(const float4*)aSrc[i]; bR[i] = *(const float4*)bSrc[i]; }
#pragma unroll
    for (int i = 0; i < 4; i++) {
        uint4 ua, ub;
        if (G2) { ua = *(const uint4*)&aR[i]; }               // act pre-rounded
        else    { ua.x=f2tf32(aR[i].x); ua.y=f2tf32(aR[i].y); ua.z=f2tf32(aR[i].z); ua.w=f2tf32(aR[i].w); }
        ub.x=f2tf32(bR[i].x); ub.y=f2tf32(bR[i].y); ub.z=f2tf32(bR[i].z); ub.w=f2tf32(bR[i].w);
        *(uint4*)(dynb + aOff[0] + aDst[i]) = ua;
        *(uint4*)(dynb + bOff[0] + bDst[i]) = ub;
    }
    __syncthreads();

    for (int kt = 0; kt < KITER; kt++) {
        const int b = kt & 1;
        if (kt + 1 < KITER) {
            const int koff = (kt + 1) * BK;
#pragma unroll
            for (int i = 0; i < 4; i++) {
                aR[i] = *(const float4*)(aSrc[i] + koff);
                bR[i] = *(const float4*)(bSrc[i] + koff);
            }
        }

        const uint32_t aB = aAddr[b] + aRowOff;
        const uint32_t bB = bAddr[b] + bRowOff;
#pragma unroll
        for (int ks = 0; ks < 4; ks++) {
            uint32_t af[4][4], bf[4][2];
#pragma unroll
            for (int mt = 0; mt < 4; mt++)
                ldsm_x4(af[mt][0], af[mt][1], af[mt][2], af[mt][3],
                        aB + mt * 2048 + aCol[ks]);
#pragma unroll
            for (int p = 0; p < 2; p++)
                ldsm_x4(bf[2*p][0], bf[2*p][1], bf[2*p+1][0], bf[2*p+1][1],
                        bB + p * 2048 + bCol[ks]);
#pragma unroll
            for (int mt = 0; mt < 4; mt++)
#pragma unroll
                for (int nt = 0; nt < 4; nt++)
                    mma_tf32(acc[mt][nt], af[mt], bf[nt]);
        }

        if (kt + 1 < KITER) {
            const int nb = b ^ 1;
#pragma unroll
            for (int i = 0; i < 4; i++) {
                uint4 ua, ub;
                if (G2) { ua = *(const uint4*)&aR[i]; }
                else    { ua.x=f2tf32(aR[i].x); ua.y=f2tf32(aR[i].y); ua.z=f2tf32(aR[i].z); ua.w=f2tf32(aR[i].w); }
                ub.x=f2tf32(bR[i].x); ub.y=f2tf32(bR[i].y); ub.z=f2tf32(bR[i].z); ub.w=f2tf32(bR[i].w);
                *(uint4*)(dynb + aOff[nb] + aDst[i]) = ua;
                *(uint4*)(dynb + bOff[nb] + bDst[i]) = ub;
            }
        }
        __syncthreads();
    }

    // epilogue
    const int g   = lane >> 2;
    const int tig = lane & 3;
#pragma unroll
    for (int mt = 0; mt < 4; mt++) {
        int r0 = wm + mt * 16 + g;
#pragma unroll
        for (int half = 0; half < 2; half++) {
            int r = r0 + half * 8;
            if (r < rowcnt) {
                int gr = rowstart + r;
                size_t cbase;
                float wgt = 1.f;
                float* C = G2 ? g_partial : g_h13;
                if (G2) {
                    cbase = (size_t)g_row_slot[gr] * HDIM + nbase;
                    wgt   = g_row_weight[gr];
                } else {
                    cbase = (size_t)gr * (size_t)N1 + nbase;
                }
#pragma unroll
                for (int nt = 0; nt < 4; nt++) {
                    int c = wn + nt * 8 + 2 * tig;
                    float2 v;
                    v.x = acc[mt][nt][half * 2 + 0] * wgt;
                    v.y = acc[mt][nt][half * 2 + 1] * wgt;
                    *(float2*)&C[cbase + c] = v;
                }
            }
        }
    }
}

// ---------------- SwiGLU (emits tf32-pre-rounded activations) ---------------
__global__ void swiglu_kernel()
{
    size_t idx = (size_t)blockIdx.x * blockDim.x + threadIdx.x;
    size_t r = idx / IDIM;
    size_t i = idx - r * IDIM;
    float v = g_h13[r * (size_t)N1 + i];
    float u = g_h13[r * (size_t)N1 + IDIM + i];
    float s = v / (1.f + __expf(-v));
    g_act[r * (size_t)IDIM + i] = __uint_as_float(f2tf32(s * u));
}

// ---------------- combine (atomic-free, deterministic) ----------------------
__global__ void combine_kernel(float* __restrict__ out)
{
    size_t idx = (size_t)blockIdx.x * blockDim.x + threadIdx.x;   // T*H
    size_t t = idx / HDIM;
    out[idx] = g_partial[idx + t * HDIM] + g_partial[idx + t * HDIM + HDIM];
}

// ---------------- launch -----------------------------------------------------
extern "C" void kernel_launch(void* const* d_in, const int* in_sizes, int n_in,
                              void* d_out, int out_size)
{
    const float* hidden = (const float*)d_in[0];
    const int*   ids    = (const int*)d_in[1];
    const float* wts    = (const float*)d_in[2];
    // d_in[3] = router_logits (unused)
    const float* w13    = (const float*)d_in[4];
    const float* w2     = (const float*)d_in[5];
    float* out = (float*)d_out;

    const int smem_bytes = 1024 + 4 * 16384;   // 66560
    cudaFuncSetAttribute(moe_gemm_ldsm<HDIM, N1, false>,
                         cudaFuncAttributeMaxDynamicSharedMemorySize, smem_bytes);
    cudaFuncSetAttribute(moe_gemm_ldsm<IDIM, HDIM, true>,
                         cudaFuncAttributeMaxDynamicSharedMemorySize, smem_bytes);

    route_kernel<<<1, 256>>>(ids, wts);

    moe_gemm_ldsm<HDIM, N1, false>
        <<<dim3(MAXTILES, N1 / BN), 256, smem_bytes>>>(hidden, w13);

    swiglu_kernel<<<(int)(((size_t)NROWS * IDIM) / 256), 256>>>();

    moe_gemm_ldsm<IDIM, HDIM, true>
        <<<dim3(MAXTILES, HDIM / BN), 256, smem_bytes>>>(nullptr, w2);

    combine_kernel<<<(int)(((size_t)TDIM * HDIM) / 256), 256>>>(out);
}

// round 4
// speedup vs baseline: 1.1591x; 1.1591x over previous
#include <cuda_runtime.h>
#include <cstdint>

#define TDIM 1024
#define HDIM 2048
#define IDIM 5632
#define NEXP 8
#define TOPK 2
#define NROWS (TDIM * TOPK)       // 2048 routed rows
#define N1 (2 * IDIM)             // 11264 (gate+up)
#define BM 128
#define BN 128
#define BK 32
#define BKP 36                    // padded K stride (elems): 144B rows, 16B aligned
#define NSTAGE 3
#define MAXTILES 24

#define STAGE_BYTES (2 * BM * BKP * 4)        // A+B per stage = 36864
#define BOFF_BYTES  (BM * BKP * 4)            // 18432

// ---------------- scratch (device globals: no allocations allowed) ----------
__device__ int   g_row_token[NROWS];
__device__ float g_row_weight[NROWS];
__device__ int   g_row_slot[NROWS];
__device__ int   g_tile_expert[MAXTILES];
__device__ int   g_tile_rowstart[MAXTILES];
__device__ int   g_tile_rowcnt[MAXTILES];
__device__ int   g_ntiles;
__device__ float g_h13[(size_t)NROWS * N1];       // 88 MB
__device__ float g_act[(size_t)NROWS * IDIM];     // 44 MB (pre-rounded to tf32)
__device__ float g_partial[(size_t)NROWS * HDIM]; // 16 MB

// ---------------- routing ---------------------------------------------------
__global__ void route_kernel(const int* __restrict__ ids, const float* __restrict__ w)
{
    __shared__ int cnt[NEXP];
    __shared__ int off[NEXP];
    __shared__ int cur[NEXP];
    int tid = threadIdx.x;
    if (tid < NEXP) cnt[tid] = 0;
    __syncthreads();
    for (int a = tid; a < NROWS; a += blockDim.x)
        atomicAdd(&cnt[ids[a]], 1);
    __syncthreads();
    if (tid == 0) {
        int s = 0;
        for (int e = 0; e < NEXP; e++) { off[e] = s; cur[e] = s; s += cnt[e]; }
        int nt = 0;
        for (int e = 0; e < NEXP; e++) {
            for (int r = 0; r < cnt[e]; r += BM) {
                g_tile_expert[nt]   = e;
                g_tile_rowstart[nt] = off[e] + r;
                g_tile_rowcnt[nt]   = min(BM, cnt[e] - r);
                nt++;
            }
        }
        g_ntiles = nt;
    }
    __syncthreads();
    for (int a = tid; a < NROWS; a += blockDim.x) {
        int e = ids[a];
        int pos = atomicAdd(&cur[e], 1);
        g_row_token[pos]  = a / TOPK;
        g_row_weight[pos] = w[a];
        g_row_slot[pos]   = a;      // t*TOPK + k
    }
}

// ---------------- helpers ----------------------------------------------------
__device__ __forceinline__ uint32_t smem_u32(const void* p)
{
    uint32_t a;
    asm("{ .reg .u64 t; cvta.to.shared.u64 t, %1; cvt.u32.u64 %0, t; }"
        : "=r"(a) : "l"(p));
    return a;
}

__device__ __forceinline__ uint32_t f2tf32(float x)
{
    uint32_t r;
    asm("cvt.rna.tf32.f32 %0, %1;" : "=r"(r) : "f"(x));
    return r;
}

__device__ __forceinline__ uint32_t cvt_raw(uint32_t raw)
{
    return f2tf32(__uint_as_float(raw));
}

#define CP_ASYNC16(dst, src) \
    asm volatile("cp.async.cg.shared.global [%0], [%1], 16;" :: "r"(dst), "l"(src) : "memory")
#define CP_COMMIT()  asm volatile("cp.async.commit_group;" ::: "memory")
#define CP_WAIT1()   asm volatile("cp.async.wait_group 1;" ::: "memory")

__device__ __forceinline__ void mma_tf32(float (&d)[4],
                                         const uint32_t (&a)[4],
                                         const uint32_t (&b)[2])
{
    asm volatile(
        "mma.sync.aligned.m16n8k8.row.col.f32.tf32.tf32.f32 "
        "{%0,%1,%2,%3}, {%4,%5,%6,%7}, {%8,%9}, {%0,%1,%2,%3};\n"
        : "+f"(d[0]), "+f"(d[1]), "+f"(d[2]), "+f"(d[3])
        : "r"(a[0]), "r"(a[1]), "r"(a[2]), "r"(a[3]),
          "r"(b[0]), "r"(b[1]));
}

// ---------------- grouped GEMM (mma.sync tf32 + cp.async 3-stage) -----------
// G2=false: h13[r, n] = sum_h hidden[token[r], h] * w13[e, n, h]
// G2=true : partial[slot[r], n] = w[r] * sum_i act[r, i] * w2[e, n, i]
template<int KDIM, int NTOT, bool G2>
__global__ void __launch_bounds__(256, 2)
moe_gemm_cp(const float* __restrict__ Asrc, const float* __restrict__ Bsrc)
{
    const int tile = blockIdx.x;
    if (tile >= g_ntiles) return;
    const int e        = g_tile_expert[tile];
    const int rowstart = g_tile_rowstart[tile];
    const int rowcnt   = g_tile_rowcnt[tile];
    const int nbase    = blockIdx.y * BN;

    extern __shared__ uint32_t dsm[];
    const uint32_t smbase = smem_u32(dsm);
    const uint32_t base   = (smbase + 127u) & ~127u;

    const int tid  = threadIdx.x;
    const int lane = tid & 31;
    const int warp = tid >> 5;
    const int wm   = (warp & 1) * 64;
    const int wn   = (warp >> 1) * 32;

    // --- staging plan: slot = tid + 256*i covers 128 rows x 8 grps of 16B ---
    const float* Aext = G2 ? (const float*)g_act : Asrc;
    const float* Bexp = Bsrc + (size_t)e * NTOT * KDIM;
    const float* aSrc[4];
    const float* bSrc[4];
    uint32_t dstOff[4];                       // byte offset within a stage half
#pragma unroll
    for (int i = 0; i < 4; i++) {
        int slot = tid + 256 * i;
        int row = slot >> 3, grp = slot & 7;
        int re = row < rowcnt ? row : rowcnt - 1;
        size_t srow = G2 ? (size_t)(rowstart + re)
                         : (size_t)g_row_token[rowstart + re];
        aSrc[i] = Aext + srow * KDIM + grp * 4;
        bSrc[i] = Bexp + (size_t)(nbase + row) * KDIM + grp * 4;
        dstOff[i] = (uint32_t)(row * (BKP * 4) + grp * 16);
    }

    float acc[4][4][4];
#pragma unroll
    for (int mt = 0; mt < 4; mt++)
#pragma unroll
        for (int nt = 0; nt < 4; nt++)
#pragma unroll
            for (int i = 0; i < 4; i++) acc[mt][nt][i] = 0.f;

    const int KITER = KDIM / BK;

    // --- prologue: issue stages 0 and 1 --------------------------------------
#pragma unroll
    for (int s = 0; s < 2; s++) {
        const uint32_t sb = base + s * STAGE_BYTES;
        const int koff = s * BK;
#pragma unroll
        for (int i = 0; i < 4; i++) {
            CP_ASYNC16(sb + dstOff[i],              aSrc[i] + koff);
            CP_ASYNC16(sb + BOFF_BYTES + dstOff[i], bSrc[i] + koff);
        }
        CP_COMMIT();
    }
    CP_WAIT1();            // stage 0 complete
    __syncthreads();

    const int g   = lane >> 2;
    const int tig = lane & 3;

    int buf = 0, nxt = 2;
    for (int kt = 0; kt < KITER; kt++) {
        // issue copies for kt+2 into the buffer freed at kt-1
        if (kt + 2 < KITER) {
            const uint32_t sb = base + nxt * STAGE_BYTES;
            const int koff = (kt + 2) * BK;
#pragma unroll
            for (int i = 0; i < 4; i++) {
                CP_ASYNC16(sb + dstOff[i],              aSrc[i] + koff);
                CP_ASYNC16(sb + BOFF_BYTES + dstOff[i], bSrc[i] + koff);
            }
        }
        CP_COMMIT();       // always commit (empty groups complete immediately)

        const uint32_t* cA = dsm + (base - smbase + buf * STAGE_BYTES) / 4;
        const uint32_t* cB = cA + BM * BKP;
#pragma unroll
        for (int ks = 0; ks < 4; ks++) {
            const int kk = ks * 8;
            uint32_t af[4][4], bf[4][2];
#pragma unroll
            for (int mt = 0; mt < 4; mt++) {
                int m0 = wm + mt * 16;
                af[mt][0] = cA[(m0 + g    ) * BKP + kk + tig];
                af[mt][1] = cA[(m0 + g + 8) * BKP + kk + tig];
                af[mt][2] = cA[(m0 + g    ) * BKP + kk + tig + 4];
                af[mt][3] = cA[(m0 + g + 8) * BKP + kk + tig + 4];
            }
#pragma unroll
            for (int nt = 0; nt < 4; nt++) {
                int n0 = wn + nt * 8;
                bf[nt][0] = cB[(n0 + g) * BKP + kk + tig];
                bf[nt][1] = cB[(n0 + g) * BKP + kk + tig + 4];
            }
            // round to tf32 after the shared load (A already rounded in G2)
            if (!G2) {
#pragma unroll
                for (int mt = 0; mt < 4; mt++)
#pragma unroll
                    for (int i = 0; i < 4; i++) af[mt][i] = cvt_raw(af[mt][i]);
            }
#pragma unroll
            for (int nt = 0; nt < 4; nt++) {
                bf[nt][0] = cvt_raw(bf[nt][0]);
                bf[nt][1] = cvt_raw(bf[nt][1]);
            }
#pragma unroll
            for (int mt = 0; mt < 4; mt++)
#pragma unroll
                for (int nt = 0; nt < 4; nt++)
                    mma_tf32(acc[mt][nt], af[mt], bf[nt]);
        }

        CP_WAIT1();        // stage kt+1 complete (only kt+2 may remain)
        __syncthreads();
        buf = buf == NSTAGE - 1 ? 0 : buf + 1;
        nxt = nxt == NSTAGE - 1 ? 0 : nxt + 1;
    }

    // --- epilogue -------------------------------------------------------------
#pragma unroll
    for (int mt = 0; mt < 4; mt++) {
        int r0 = wm + mt * 16 + g;
#pragma unroll
        for (int half = 0; half < 2; half++) {
            int r = r0 + half * 8;
            if (r < rowcnt) {
                int gr = rowstart + r;
                size_t cbase;
                float wgt = 1.f;
                float* C = G2 ? g_partial : g_h13;
                if (G2) {
                    cbase = (size_t)g_row_slot[gr] * HDIM + nbase;
                    wgt   = g_row_weight[gr];
                } else {
                    cbase = (size_t)gr * (size_t)N1 + nbase;
                }
#pragma unroll
                for (int nt = 0; nt < 4; nt++) {
                    int c = wn + nt * 8 + 2 * tig;
                    float2 v;
                    v.x = acc[mt][nt][half * 2 + 0] * wgt;
                    v.y = acc[mt][nt][half * 2 + 1] * wgt;
                    *(float2*)&C[cbase + c] = v;
                }
            }
        }
    }
}

// ---------------- SwiGLU (emits tf32-pre-rounded activations) ---------------
__global__ void swiglu_kernel()
{
    size_t idx = (size_t)blockIdx.x * blockDim.x + threadIdx.x;
    size_t r = idx / IDIM;
    size_t i = idx - r * IDIM;
    float v = g_h13[r * (size_t)N1 + i];
    float u = g_h13[r * (size_t)N1 + IDIM + i];
    float s = v / (1.f + __expf(-v));
    g_act[r * (size_t)IDIM + i] = __uint_as_float(f2tf32(s * u));
}

// ---------------- combine (atomic-free, deterministic) ----------------------
__global__ void combine_kernel(float* __restrict__ out)
{
    size_t idx = (size_t)blockIdx.x * blockDim.x + threadIdx.x;   // T*H
    size_t t = idx / HDIM;
    out[idx] = g_partial[idx + t * HDIM] + g_partial[idx + t * HDIM + HDIM];
}

// ---------------- launch -----------------------------------------------------
extern "C" void kernel_launch(void* const* d_in, const int* in_sizes, int n_in,
                              void* d_out, int out_size)
{
    const float* hidden = (const float*)d_in[0];
    const int*   ids    = (const int*)d_in[1];
    const float* wts    = (const float*)d_in[2];
    // d_in[3] = router_logits (unused)
    const float* w13    = (const float*)d_in[4];
    const float* w2     = (const float*)d_in[5];
    float* out = (float*)d_out;

    const int smem_bytes = 128 + NSTAGE * STAGE_BYTES;   // 110720
    cudaFuncSetAttribute(moe_gemm_cp<HDIM, N1, false>,
                         cudaFuncAttributeMaxDynamicSharedMemorySize, smem_bytes);
    cudaFuncSetAttribute(moe_gemm_cp<IDIM, HDIM, true>,
                         cudaFuncAttributeMaxDynamicSharedMemorySize, smem_bytes);

    route_kernel<<<1, 256>>>(ids, wts);

    moe_gemm_cp<HDIM, N1, false>
        <<<dim3(MAXTILES, N1 / BN), 256, smem_bytes>>>(hidden, w13);

    swiglu_kernel<<<(int)(((size_t)NROWS * IDIM) / 256), 256>>>();

    moe_gemm_cp<IDIM, HDIM, true>
        <<<dim3(MAXTILES, HDIM / BN), 256, smem_bytes>>>(nullptr, w2);

    combine_kernel<<<(int)(((size_t)TDIM * HDIM) / 256), 256>>>(out);
}

// round 5
// speedup vs baseline: 1.7584x; 1.5170x over previous
#include <cuda_runtime.h>
#include <cuda_fp16.h>
#include <cstdint>

#define TDIM 1024
#define HDIM 2048
#define IDIM 5632
#define NEXP 8
#define TOPK 2
#define NROWS (TDIM * TOPK)       // 2048 routed rows
#define N1 (2 * IDIM)             // 11264 (gate+up)
#define BM 128
#define BN 128
#define BK 32
#define BKPA 40                   // A row stride (fp16 elems) = 80B: conflict-free
#define BKPB 36                   // B row stride (f32 elems)  = 144B
#define NSTAGE 3
#define MAXTILES 24

#define ASTAGE (BM * BKPA * 2)              // 10240 B
#define BSTAGE (BN * BKPB * 4)              // 18432 B
#define STAGE_BYTES (ASTAGE + BSTAGE)       // 28672 B

// ---------------- scratch (device globals: no allocations allowed) ----------
__device__ int    g_row_token[NROWS];
__device__ float  g_row_weight[NROWS];
__device__ int    g_row_slot[NROWS];
__device__ int    g_tile_expert[MAXTILES];
__device__ int    g_tile_rowstart[MAXTILES];
__device__ int    g_tile_rowcnt[MAXTILES];
__device__ int    g_ntiles;
__device__ __half g_hidden_h[(size_t)TDIM * HDIM];   // 4 MB  (fp16 hidden)
__device__ float  g_h13[(size_t)NROWS * N1];         // 88 MB
__device__ __half g_act_h[(size_t)NROWS * IDIM];     // 22 MB (fp16 activations)
__device__ float  g_partial[(size_t)NROWS * HDIM];   // 16 MB

// ---------------- routing ---------------------------------------------------
__global__ void route_kernel(const int* __restrict__ ids, const float* __restrict__ w)
{
    __shared__ int cnt[NEXP];
    __shared__ int off[NEXP];
    __shared__ int cur[NEXP];
    int tid = threadIdx.x;
    if (tid < NEXP) cnt[tid] = 0;
    __syncthreads();
    for (int a = tid; a < NROWS; a += blockDim.x)
        atomicAdd(&cnt[ids[a]], 1);
    __syncthreads();
    if (tid == 0) {
        int s = 0;
        for (int e = 0; e < NEXP; e++) { off[e] = s; cur[e] = s; s += cnt[e]; }
        int nt = 0;
        for (int e = 0; e < NEXP; e++) {
            for (int r = 0; r < cnt[e]; r += BM) {
                g_tile_expert[nt]   = e;
                g_tile_rowstart[nt] = off[e] + r;
                g_tile_rowcnt[nt]   = min(BM, cnt[e] - r);
                nt++;
            }
        }
        g_ntiles = nt;
    }
    __syncthreads();
    for (int a = tid; a < NROWS; a += blockDim.x) {
        int e = ids[a];
        int pos = atomicAdd(&cur[e], 1);
        g_row_token[pos]  = a / TOPK;
        g_row_weight[pos] = w[a];
        g_row_slot[pos]   = a;      // t*TOPK + k
    }
}

// ---------------- hidden f32 -> fp16 -----------------------------------------
__global__ void hconv_kernel(const float* __restrict__ src)
{
    size_t i = (size_t)blockIdx.x * blockDim.x + threadIdx.x;   // T*H exact
    float2 v = *(const float2*)(src + 2 * i);
    *(__half2*)&g_hidden_h[2 * i] = __floats2half2_rn(v.x, v.y);
}

// ---------------- helpers ----------------------------------------------------
__device__ __forceinline__ uint32_t smem_u32(const void* p)
{
    uint32_t a;
    asm("{ .reg .u64 t; cvta.to.shared.u64 t, %1; cvt.u32.u64 %0, t; }"
        : "=r"(a) : "l"(p));
    return a;
}

__device__ __forceinline__ uint32_t packh2(float lo, float hi)
{
    uint32_t d;
    asm("cvt.rn.f16x2.f32 %0, %1, %2;" : "=r"(d) : "f"(hi), "f"(lo));
    return d;
}

#define CP_ASYNC16(dst, src) \
    asm volatile("cp.async.cg.shared.global [%0], [%1], 16;" :: "r"(dst), "l"(src) : "memory")
#define CP_COMMIT()  asm volatile("cp.async.commit_group;" ::: "memory")
#define CP_WAIT1()   asm volatile("cp.async.wait_group 1;" ::: "memory")

__device__ __forceinline__ void mma_f16(float (&d)[4],
                                        const uint32_t (&a)[4],
                                        const uint32_t (&b)[2])
{
    asm volatile(
        "mma.sync.aligned.m16n8k16.row.col.f32.f16.f16.f32 "
        "{%0,%1,%2,%3}, {%4,%5,%6,%7}, {%8,%9}, {%0,%1,%2,%3};\n"
        : "+f"(d[0]), "+f"(d[1]), "+f"(d[2]), "+f"(d[3])
        : "r"(a[0]), "r"(a[1]), "r"(a[2]), "r"(a[3]),
          "r"(b[0]), "r"(b[1]));
}

// ---------------- grouped GEMM (fp16 mma.sync + cp.async 3-stage) -----------
// G2=false: h13[r, n] = sum_h hidden_h[token[r], h] * w13[e, n, h]
// G2=true : partial[slot[r], n] = w[r] * sum_i act_h[r, i] * w2[e, n, i]
// A in smem: fp16 [128][BKPA]; B in smem: f32 [128][BKPB] (cvt after LDS)
template<int KDIM, int NTOT, bool G2>
__global__ void __launch_bounds__(256, 2)
moe_gemm_h(const float* __restrict__ Bsrc)
{
    const int tile = blockIdx.x;
    if (tile >= g_ntiles) return;
    const int e        = g_tile_expert[tile];
    const int rowstart = g_tile_rowstart[tile];
    const int rowcnt   = g_tile_rowcnt[tile];
    const int nbase    = blockIdx.y * BN;

    extern __shared__ uint32_t dsm[];
    const uint32_t smbase = smem_u32(dsm);
    const uint32_t base   = (smbase + 127u) & ~127u;
    char* dynb            = (char*)dsm + (base - smbase);

    const int tid  = threadIdx.x;
    const int lane = tid & 31;
    const int warp = tid >> 5;
    const int wm   = (warp & 1) * 64;
    const int wn   = (warp >> 1) * 32;
    const int g    = lane >> 2;
    const int tig  = lane & 3;

    // --- staging plans --------------------------------------------------------
    const __half* Ah = G2 ? g_act_h : g_hidden_h;
    const float*  Bexp = Bsrc + (size_t)e * NTOT * KDIM;

    // A: 128 rows x 64B data (32 fp16) = 512 chunks of 16B -> 2 per thread
    const __half* aSrc[2]; uint32_t aOffDst[2];
#pragma unroll
    for (int i = 0; i < 2; i++) {
        int slot = tid + 256 * i;
        int row = slot >> 2, grp = slot & 3;
        int re = row < rowcnt ? row : rowcnt - 1;
        size_t srow = G2 ? (size_t)(rowstart + re)
                         : (size_t)g_row_token[rowstart + re];
        aSrc[i]    = Ah + srow * KDIM + grp * 8;
        aOffDst[i] = (uint32_t)(row * (BKPA * 2) + grp * 16);
    }
    // B: 128 rows x 128B data = 1024 chunks -> 4 per thread
    const float* bSrc[4]; uint32_t bOffDst[4];
#pragma unroll
    for (int i = 0; i < 4; i++) {
        int slot = tid + 256 * i;
        int row = slot >> 3, grp = slot & 7;
        bSrc[i]    = Bexp + (size_t)(nbase + row) * KDIM + grp * 4;
        bOffDst[i] = (uint32_t)(ASTAGE + row * (BKPB * 4) + grp * 16);
    }

    float acc[4][4][4];
#pragma unroll
    for (int mt = 0; mt < 4; mt++)
#pragma unroll
        for (int nt = 0; nt < 4; nt++)
#pragma unroll
            for (int i = 0; i < 4; i++) acc[mt][nt][i] = 0.f;

    const int KITER = KDIM / BK;

    // --- prologue: issue stages 0,1 ------------------------------------------
#pragma unroll
    for (int s = 0; s < 2; s++) {
        const uint32_t sb = base + s * STAGE_BYTES;
#pragma unroll
        for (int i = 0; i < 2; i++)
            CP_ASYNC16(sb + aOffDst[i], aSrc[i] + s * BK);
#pragma unroll
        for (int i = 0; i < 4; i++)
            CP_ASYNC16(sb + bOffDst[i], bSrc[i] + s * BK);
        CP_COMMIT();
    }
    CP_WAIT1();
    __syncthreads();

    // fragment base offsets (within stage)
    const uint32_t aFB = (uint32_t)((wm + g) * (BKPA * 2) + tig * 4);
    const uint32_t bFB = (uint32_t)(ASTAGE + (wn + g) * (BKPB * 4) + tig * 8);

    int buf = 0, nxt = 2;
    for (int kt = 0; kt < KITER; kt++) {
        if (kt + 2 < KITER) {
            const uint32_t sb = base + nxt * STAGE_BYTES;
#pragma unroll
            for (int i = 0; i < 2; i++)
                CP_ASYNC16(sb + aOffDst[i], aSrc[i] + (kt + 2) * BK);
#pragma unroll
            for (int i = 0; i < 4; i++)
                CP_ASYNC16(sb + bOffDst[i], bSrc[i] + (kt + 2) * BK);
        }
        CP_COMMIT();

        char* sbuf = dynb + buf * STAGE_BYTES;
#pragma unroll
        for (int ks = 0; ks < 2; ks++) {
            uint32_t af[4][4], bf[4][2];
            const char* ab = sbuf + aFB + ks * 32;   // k16 = 32B fp16
            const char* bb = sbuf + bFB + ks * 64;   // k16 = 64B f32
#pragma unroll
            for (int mt = 0; mt < 4; mt++) {
                const char* p = ab + mt * (16 * BKPA * 2);
                af[mt][0] = *(const uint32_t*)(p);                      // (g,   k0..1)
                af[mt][1] = *(const uint32_t*)(p + 8 * BKPA * 2);       // (g+8, k0..1)
                af[mt][2] = *(const uint32_t*)(p + 16);                 // (g,   k8..9)
                af[mt][3] = *(const uint32_t*)(p + 8 * BKPA * 2 + 16);  // (g+8, k8..9)
            }
#pragma unroll
            for (int nt = 0; nt < 4; nt++) {
                const char* p = bb + nt * (8 * BKPB * 4);
                float2 lo = *(const float2*)(p);        // k = 2tig, 2tig+1
                float2 hi = *(const float2*)(p + 32);   // k = 2tig+8, 2tig+9
                bf[nt][0] = packh2(lo.x, lo.y);
                bf[nt][1] = packh2(hi.x, hi.y);
            }
#pragma unroll
            for (int mt = 0; mt < 4; mt++)
#pragma unroll
                for (int nt = 0; nt < 4; nt++)
                    mma_f16(acc[mt][nt], af[mt], bf[nt]);
        }

        CP_WAIT1();
        __syncthreads();
        buf = buf == NSTAGE - 1 ? 0 : buf + 1;
        nxt = nxt == NSTAGE - 1 ? 0 : nxt + 1;
    }

    // --- epilogue --------------------------------------------------------------
#pragma unroll
    for (int mt = 0; mt < 4; mt++) {
        int r0 = wm + mt * 16 + g;
#pragma unroll
        for (int half = 0; half < 2; half++) {
            int r = r0 + half * 8;
            if (r < rowcnt) {
                int gr = rowstart + r;
                size_t cbase;
                float wgt = 1.f;
                float* C = G2 ? g_partial : g_h13;
                if (G2) {
                    cbase = (size_t)g_row_slot[gr] * HDIM + nbase;
                    wgt   = g_row_weight[gr];
                } else {
                    cbase = (size_t)gr * (size_t)N1 + nbase;
                }
#pragma unroll
                for (int nt = 0; nt < 4; nt++) {
                    int c = wn + nt * 8 + 2 * tig;
                    float2 v;
                    v.x = acc[mt][nt][half * 2 + 0] * wgt;
                    v.y = acc[mt][nt][half * 2 + 1] * wgt;
                    *(float2*)&C[cbase + c] = v;
                }
            }
        }
    }
}

// ---------------- SwiGLU (emits fp16 activations) ----------------------------
__global__ void swiglu_kernel()
{
    size_t idx = (size_t)blockIdx.x * blockDim.x + threadIdx.x;
    size_t r = idx / IDIM;
    size_t i = idx - r * IDIM;
    float v = g_h13[r * (size_t)N1 + i];
    float u = g_h13[r * (size_t)N1 + IDIM + i];
    float s = v / (1.f + __expf(-v));
    g_act_h[r * (size_t)IDIM + i] = __float2half_rn(s * u);
}

// ---------------- combine (atomic-free, deterministic) ----------------------
__global__ void combine_kernel(float* __restrict__ out)
{
    size_t idx = (size_t)blockIdx.x * blockDim.x + threadIdx.x;   // T*H
    size_t t = idx / HDIM;
    out[idx] = g_partial[idx + t * HDIM] + g_partial[idx + t * HDIM + HDIM];
}

// ---------------- launch -----------------------------------------------------
extern "C" void kernel_launch(void* const* d_in, const int* in_sizes, int n_in,
                              void* d_out, int out_size)
{
    const float* hidden = (const float*)d_in[0];
    const int*   ids    = (const int*)d_in[1];
    const float* wts    = (const float*)d_in[2];
    // d_in[3] = router_logits (unused)
    const float* w13    = (const float*)d_in[4];
    const float* w2     = (const float*)d_in[5];
    float* out = (float*)d_out;

    const int smem_bytes = 128 + NSTAGE * STAGE_BYTES;   // 86144
    cudaFuncSetAttribute(moe_gemm_h<HDIM, N1, false>,
                         cudaFuncAttributeMaxDynamicSharedMemorySize, smem_bytes);
    cudaFuncSetAttribute(moe_gemm_h<IDIM, HDIM, true>,
                         cudaFuncAttributeMaxDynamicSharedMemorySize, smem_bytes);

    route_kernel<<<1, 256>>>(ids, wts);
    hconv_kernel<<<(TDIM * HDIM / 2) / 256, 256>>>(hidden);

    moe_gemm_h<HDIM, N1, false>
        <<<dim3(MAXTILES, N1 / BN), 256, smem_bytes>>>(w13);

    swiglu_kernel<<<(int)(((size_t)NROWS * IDIM) / 256), 256>>>();

    moe_gemm_h<IDIM, HDIM, true>
        <<<dim3(MAXTILES, HDIM / BN), 256, smem_bytes>>>(w2);

    combine_kernel<<<(int)(((size_t)TDIM * HDIM) / 256), 256>>>(out);
}

// round 6
// speedup vs baseline: 1.7851x; 1.0152x over previous
#include <cuda_runtime.h>
#include <cuda_fp16.h>
#include <cstdint>

#define TDIM 1024
#define HDIM 2048
#define IDIM 5632
#define NEXP 8
#define TOPK 2
#define NROWS (TDIM * TOPK)       // 2048 routed rows
#define N1 (2 * IDIM)             // 11264 (gate+up)
#define BM 128
#define BN 128
#define BK 32
#define BKPA 48                   // A row stride (fp16 elems) = 96B: phase-disjoint banks
#define BKPB 36                   // B row stride (f32 elems)  = 144B
#define NSTAGE 3
#define MAXTILES 24

#define ASTAGE (BM * BKPA * 2)              // 12288 B
#define BSTAGE (BN * BKPB * 4)              // 18432 B
#define STAGE_BYTES (ASTAGE + BSTAGE)       // 30720 B

// ---------------- scratch (device globals: no allocations allowed) ----------
__device__ int    g_row_token[NROWS];
__device__ float  g_row_weight[NROWS];
__device__ int    g_row_slot[NROWS];
__device__ int    g_tile_expert[MAXTILES];
__device__ int    g_tile_rowstart[MAXTILES];
__device__ int    g_tile_rowcnt[MAXTILES];
__device__ int    g_ntiles;
__device__ __half g_hidden_h[(size_t)TDIM * HDIM];   // 4 MB  (fp16, k-permuted)
__device__ __half g_act_h[(size_t)NROWS * IDIM];     // 22 MB (fp16, k-permuted)
__device__ float  g_partial[(size_t)NROWS * HDIM];   // 16 MB

// k-pair permutation within each 16-element group: storage slot of pair p
// order (0,4,1,5,2,6,3,7) -> fragment pairs (tig, tig+4) land adjacent.
__device__ __forceinline__ int pslot(int p) { return (p & 3) * 2 + (p >> 2); }

// ---------------- routing ---------------------------------------------------
__global__ void route_kernel(const int* __restrict__ ids, const float* __restrict__ w)
{
    __shared__ int cnt[NEXP];
    __shared__ int off[NEXP];
    __shared__ int cur[NEXP];
    int tid = threadIdx.x;
    if (tid < NEXP) cnt[tid] = 0;
    __syncthreads();
    for (int a = tid; a < NROWS; a += blockDim.x)
        atomicAdd(&cnt[ids[a]], 1);
    __syncthreads();
    if (tid == 0) {
        int s = 0;
        for (int e = 0; e < NEXP; e++) { off[e] = s; cur[e] = s; s += cnt[e]; }
        int nt = 0;
        for (int e = 0; e < NEXP; e++) {
            for (int r = 0; r < cnt[e]; r += BM) {
                g_tile_expert[nt]   = e;
                g_tile_rowstart[nt] = off[e] + r;
                g_tile_rowcnt[nt]   = min(BM, cnt[e] - r);
                nt++;
            }
        }
        g_ntiles = nt;
    }
    __syncthreads();
    for (int a = tid; a < NROWS; a += blockDim.x) {
        int e = ids[a];
        int pos = atomicAdd(&cur[e], 1);
        g_row_token[pos]  = a / TOPK;
        g_row_weight[pos] = w[a];
        g_row_slot[pos]   = a;      // t*TOPK + k
    }
}

// ---------------- hidden f32 -> fp16 (k-permuted) ----------------------------
__global__ void hconv_kernel(const float* __restrict__ src)
{
    size_t i = (size_t)blockIdx.x * blockDim.x + threadIdx.x;   // pair index
    float2 v = *(const float2*)(src + 2 * i);
    size_t t  = i / (HDIM / 2);
    int   kp  = (int)(i % (HDIM / 2));
    int   g16 = kp >> 3, p = kp & 7;
    *(__half2*)&g_hidden_h[t * HDIM + g16 * 16 + pslot(p) * 2] =
        __floats2half2_rn(v.x, v.y);
}

// ---------------- helpers ----------------------------------------------------
__device__ __forceinline__ uint32_t smem_u32(const void* p)
{
    uint32_t a;
    asm("{ .reg .u64 t; cvta.to.shared.u64 t, %1; cvt.u32.u64 %0, t; }"
        : "=r"(a) : "l"(p));
    return a;
}

__device__ __forceinline__ uint32_t packh2(float lo, float hi)
{
    uint32_t d;
    asm("cvt.rn.f16x2.f32 %0, %1, %2;" : "=r"(d) : "f"(hi), "f"(lo));
    return d;
}

#define CP_ASYNC16(dst, src) \
    asm volatile("cp.async.cg.shared.global [%0], [%1], 16;" :: "r"(dst), "l"(src) : "memory")
#define CP_COMMIT()  asm volatile("cp.async.commit_group;" ::: "memory")
#define CP_WAIT1()   asm volatile("cp.async.wait_group 1;" ::: "memory")

__device__ __forceinline__ void mma_f16(float (&d)[4],
                                        const uint32_t (&a)[4],
                                        const uint32_t (&b)[2])
{
    asm volatile(
        "mma.sync.aligned.m16n8k16.row.col.f32.f16.f16.f32 "
        "{%0,%1,%2,%3}, {%4,%5,%6,%7}, {%8,%9}, {%0,%1,%2,%3};\n"
        : "+f"(d[0]), "+f"(d[1]), "+f"(d[2]), "+f"(d[3])
        : "r"(a[0]), "r"(a[1]), "r"(a[2]), "r"(a[3]),
          "r"(b[0]), "r"(b[1]));
}

// ---------------- grouped GEMM (fp16 mma.sync + cp.async 3-stage) -----------
// G2=false (GEMM1 fused): B rows interleave w13 gate/up; epilogue does SwiGLU
//   and writes fp16 act (k-permuted). y-block covers 64 act columns.
// G2=true  (GEMM2): partial[slot[r], n] = w[r] * sum_i act[r,i] * w2[e,n,i]
template<int KDIM, bool G2>
__global__ void __launch_bounds__(256, 2)
moe_gemm_h(const float* __restrict__ Bsrc)
{
    const int tile = blockIdx.x;
    if (tile >= g_ntiles) return;
    const int e        = g_tile_expert[tile];
    const int rowstart = g_tile_rowstart[tile];
    const int rowcnt   = g_tile_rowcnt[tile];
    const int nbase    = blockIdx.y * (G2 ? BN : 64);

    extern __shared__ uint32_t dsm[];
    const uint32_t smbase = smem_u32(dsm);
    const uint32_t base   = (smbase + 127u) & ~127u;
    char* dynb            = (char*)dsm + (base - smbase);

    const int tid  = threadIdx.x;
    const int lane = tid & 31;
    const int warp = tid >> 5;
    const int wm   = (warp & 1) * 64;
    const int wn   = (warp >> 1) * 32;
    const int g    = lane >> 2;
    const int tig  = lane & 3;

    // --- staging plans --------------------------------------------------------
    const __half* Ah   = G2 ? g_act_h : g_hidden_h;
    const int     NTOT = G2 ? HDIM : N1;
    const float*  Bexp = Bsrc + (size_t)e * NTOT * KDIM;

    // A: 128 rows x 64B (32 fp16) = 512 chunks of 16B -> 2 per thread
    const __half* aSrc[2]; uint32_t aOffDst[2];
#pragma unroll
    for (int i = 0; i < 2; i++) {
        int slot = tid + 256 * i;
        int row = slot >> 2, grp = slot & 3;
        int re = row < rowcnt ? row : rowcnt - 1;
        size_t srow = G2 ? (size_t)(rowstart + re)
                         : (size_t)g_row_token[rowstart + re];
        aSrc[i]    = Ah + srow * KDIM + grp * 8;
        aOffDst[i] = (uint32_t)(row * (BKPA * 2) + grp * 16);
    }
    // B: 128 rows x 128B = 1024 chunks -> 4 per thread
    const float* bSrc[4]; uint32_t bOffDst[4];
#pragma unroll
    for (int i = 0; i < 4; i++) {
        int slot = tid + 256 * i;
        int row = slot >> 3, grp = slot & 7;
        int srcrow = G2 ? (nbase + row)
                        : ((row & 1) ? IDIM : 0) + nbase + (row >> 1);
        bSrc[i]    = Bexp + (size_t)srcrow * KDIM + grp * 4;
        bOffDst[i] = (uint32_t)(ASTAGE + row * (BKPB * 4) + grp * 16);
    }

    float acc[4][4][4];
#pragma unroll
    for (int mt = 0; mt < 4; mt++)
#pragma unroll
        for (int nt = 0; nt < 4; nt++)
#pragma unroll
            for (int i = 0; i < 4; i++) acc[mt][nt][i] = 0.f;

    const int KITER = KDIM / BK;

    // --- prologue: issue stages 0,1 ------------------------------------------
#pragma unroll
    for (int s = 0; s < 2; s++) {
        const uint32_t sb = base + s * STAGE_BYTES;
#pragma unroll
        for (int i = 0; i < 2; i++)
            CP_ASYNC16(sb + aOffDst[i], aSrc[i] + s * BK);
#pragma unroll
        for (int i = 0; i < 4; i++)
            CP_ASYNC16(sb + bOffDst[i], bSrc[i] + s * BK);
        CP_COMMIT();
    }
    CP_WAIT1();
    __syncthreads();

    // fragment base offsets (within stage)
    const uint32_t aFB = (uint32_t)((wm + g) * (BKPA * 2) + tig * 8);
    const uint32_t bFB = (uint32_t)(ASTAGE + (wn + g) * (BKPB * 4) + tig * 8);

    int buf = 0, nxt = 2;
    for (int kt = 0; kt < KITER; kt++) {
        if (kt + 2 < KITER) {
            const uint32_t sb = base + nxt * STAGE_BYTES;
#pragma unroll
            for (int i = 0; i < 2; i++)
                CP_ASYNC16(sb + aOffDst[i], aSrc[i] + (kt + 2) * BK);
#pragma unroll
            for (int i = 0; i < 4; i++)
                CP_ASYNC16(sb + bOffDst[i], bSrc[i] + (kt + 2) * BK);
        }
        CP_COMMIT();

        char* sbuf = dynb + buf * STAGE_BYTES;
#pragma unroll
        for (int ks = 0; ks < 2; ks++) {
            uint32_t af[4][4], bf[4][2];
            const char* ab = sbuf + aFB + ks * 32;   // k16 group = 32B fp16
            const char* bb = sbuf + bFB + ks * 64;   // k16 group = 64B f32
#pragma unroll
            for (int mt = 0; mt < 4; mt++) {
                const char* p = ab + mt * (16 * BKPA * 2);
                // permuted layout: slots (2tig, 2tig+1) = orig pairs (tig, tig+4)
                uint2 lo = *(const uint2*)(p);                      // row g
                uint2 hi = *(const uint2*)(p + 8 * BKPA * 2);       // row g+8
                af[mt][0] = lo.x;   // (g,   k 2tig..2tig+1)
                af[mt][1] = hi.x;   // (g+8, k 2tig..2tig+1)
                af[mt][2] = lo.y;   // (g,   k 2tig+8..2tig+9)
                af[mt][3] = hi.y;   // (g+8, k 2tig+8..2tig+9)
            }
#pragma unroll
            for (int nt = 0; nt < 4; nt++) {
                const char* p = bb + nt * (8 * BKPB * 4);
                float2 lo = *(const float2*)(p);        // k = 2tig, 2tig+1
                float2 hi = *(const float2*)(p + 32);   // k = 2tig+8, 2tig+9
                bf[nt][0] = packh2(lo.x, lo.y);
                bf[nt][1] = packh2(hi.x, hi.y);
            }
#pragma unroll
            for (int mt = 0; mt < 4; mt++)
#pragma unroll
                for (int nt = 0; nt < 4; nt++)
                    mma_f16(acc[mt][nt], af[mt], bf[nt]);
        }

        CP_WAIT1();
        __syncthreads();
        buf = buf == NSTAGE - 1 ? 0 : buf + 1;
        nxt = nxt == NSTAGE - 1 ? 0 : nxt + 1;
    }

    // --- epilogue --------------------------------------------------------------
#pragma unroll
    for (int mt = 0; mt < 4; mt++) {
        int r0 = wm + mt * 16 + g;
#pragma unroll
        for (int half = 0; half < 2; half++) {
            int r = r0 + half * 8;
            if (r < rowcnt) {
                int gr = rowstart + r;
                if (G2) {
                    size_t cbase = (size_t)g_row_slot[gr] * HDIM + nbase;
                    float  wgt   = g_row_weight[gr];
#pragma unroll
                    for (int nt = 0; nt < 4; nt++) {
                        int c = wn + nt * 8 + 2 * tig;
                        float2 v;
                        v.x = acc[mt][nt][half * 2 + 0] * wgt;
                        v.y = acc[mt][nt][half * 2 + 1] * wgt;
                        *(float2*)&g_partial[cbase + c] = v;
                    }
                } else {
                    // fused SwiGLU: even col = gate, odd col = up of act col
                    size_t rb = (size_t)gr * IDIM;
#pragma unroll
                    for (int nt = 0; nt < 4; nt++) {
                        float x = acc[mt][nt][half * 2 + 0];
                        float u = acc[mt][nt][half * 2 + 1];
                        float a = (x / (1.f + __expf(-x))) * u;
                        int aj = nbase + (wn >> 1) + nt * 4 + tig;  // global act col
                        int p  = (aj >> 1) & 7;
                        int pj = (aj & ~15) + pslot(p) * 2 + (aj & 1);
                        g_act_h[rb + pj] = __float2half_rn(a);
                    }
                }
            }
        }
    }
}

// ---------------- combine (atomic-free, deterministic) ----------------------
__global__ void combine_kernel(float* __restrict__ out)
{
    size_t idx = (size_t)blockIdx.x * blockDim.x + threadIdx.x;   // T*H
    size_t t = idx / HDIM;
    out[idx] = g_partial[idx + t * HDIM] + g_partial[idx + t * HDIM + HDIM];
}

// ---------------- launch -----------------------------------------------------
extern "C" void kernel_launch(void* const* d_in, const int* in_sizes, int n_in,
                              void* d_out, int out_size)
{
    const float* hidden = (const float*)d_in[0];
    const int*   ids    = (const int*)d_in[1];
    const float* wts    = (const float*)d_in[2];
    // d_in[3] = router_logits (unused)
    const float* w13    = (const float*)d_in[4];
    const float* w2     = (const float*)d_in[5];
    float* out = (float*)d_out;

    const int smem_bytes = 128 + NSTAGE * STAGE_BYTES;   // 92288
    cudaFuncSetAttribute(moe_gemm_h<HDIM, false>,
                         cudaFuncAttributeMaxDynamicSharedMemorySize, smem_bytes);
    cudaFuncSetAttribute(moe_gemm_h<IDIM, true>,
                         cudaFuncAttributeMaxDynamicSharedMemorySize, smem_bytes);

    route_kernel<<<1, 256>>>(ids, wts);
    hconv_kernel<<<(TDIM * HDIM / 2) / 256, 256>>>(hidden);

    // GEMM1 (fused SwiGLU): each y-block produces 64 act columns
    moe_gemm_h<HDIM, false>
        <<<dim3(MAXTILES, IDIM / 64), 256, smem_bytes>>>(w13);

    moe_gemm_h<IDIM, true>
        <<<dim3(MAXTILES, HDIM / BN), 256, smem_bytes>>>(w2);

    combine_kernel<<<(int)(((size_t)TDIM * HDIM) / 256), 256>>>(out);
}

// round 7
// speedup vs baseline: 2.2266x; 1.2473x over previous
#include <cuda_runtime.h>
#include <cuda_fp16.h>
#include <cstdint>

#define TDIM 1024
#define HDIM 2048
#define IDIM 5632
#define NEXP 8
#define TOPK 2
#define NROWS (TDIM * TOPK)       // 2048 routed rows
#define N1 (2 * IDIM)             // 11264 (gate+up)
#define BM 128
#define BN 128
#define BK 32
#define BKPA 48                   // A row stride (fp16 elems) = 96B: conflict-free LDS.64
#define BKPB 40                   // B row stride (f32 elems)  = 160B: conflict-free LDS.64
#define NSTAGE 3
#define MAXTILES 24
#define KSPLIT 2                  // GEMM2 split-K factor

#define ASTAGE (BM * BKPA * 2)              // 12288 B
#define BSTAGE (BN * BKPB * 4)              // 20480 B
#define STAGE_BYTES (ASTAGE + BSTAGE)       // 32768 B

// ---------------- scratch (device globals: no allocations allowed) ----------
__device__ int    g_row_token[NROWS];
__device__ float  g_row_weight[NROWS];
__device__ int    g_row_slot[NROWS];
__device__ int    g_tile_expert[MAXTILES];
__device__ int    g_tile_rowstart[MAXTILES];
__device__ int    g_tile_rowcnt[MAXTILES];
__device__ int    g_ntiles;
__device__ __half g_hidden_h[(size_t)TDIM * HDIM];            // 4 MB (fp16, k-permuted)
__device__ __half g_act_h[(size_t)NROWS * IDIM];              // 22 MB (fp16, k-permuted)
__device__ float  g_partial[(size_t)KSPLIT * NROWS * HDIM];   // 32 MB

// k-pair permutation within each 16-element group: storage slot of pair p
// order (0,4,1,5,2,6,3,7) -> fragment pairs (tig, tig+4) land adjacent.
__device__ __forceinline__ int pslot(int p) { return (p & 3) * 2 + (p >> 2); }

// ---------------- routing ---------------------------------------------------
__global__ void route_kernel(const int* __restrict__ ids, const float* __restrict__ w)
{
    __shared__ int cnt[NEXP];
    __shared__ int off[NEXP];
    __shared__ int cur[NEXP];
    int tid = threadIdx.x;
    if (tid < NEXP) cnt[tid] = 0;
    __syncthreads();
    for (int a = tid; a < NROWS; a += blockDim.x)
        atomicAdd(&cnt[ids[a]], 1);
    __syncthreads();
    if (tid == 0) {
        int s = 0;
        for (int e = 0; e < NEXP; e++) { off[e] = s; cur[e] = s; s += cnt[e]; }
        int nt = 0;
        for (int e = 0; e < NEXP; e++) {
            for (int r = 0; r < cnt[e]; r += BM) {
                g_tile_expert[nt]   = e;
                g_tile_rowstart[nt] = off[e] + r;
                g_tile_rowcnt[nt]   = min(BM, cnt[e] - r);
                nt++;
            }
        }
        g_ntiles = nt;
    }
    __syncthreads();
    for (int a = tid; a < NROWS; a += blockDim.x) {
        int e = ids[a];
        int pos = atomicAdd(&cur[e], 1);
        g_row_token[pos]  = a / TOPK;
        g_row_weight[pos] = w[a];
        g_row_slot[pos]   = a;      // t*TOPK + k
    }
}

// ---------------- hidden f32 -> fp16 (k-permuted) ----------------------------
__global__ void hconv_kernel(const float* __restrict__ src)
{
    size_t i = (size_t)blockIdx.x * blockDim.x + threadIdx.x;   // pair index
    float2 v = *(const float2*)(src + 2 * i);
    size_t t  = i / (HDIM / 2);
    int   kp  = (int)(i % (HDIM / 2));
    int   g16 = kp >> 3, p = kp & 7;
    *(__half2*)&g_hidden_h[t * HDIM + g16 * 16 + pslot(p) * 2] =
        __floats2half2_rn(v.x, v.y);
}

// ---------------- helpers ----------------------------------------------------
__device__ __forceinline__ uint32_t smem_u32(const void* p)
{
    uint32_t a;
    asm("{ .reg .u64 t; cvta.to.shared.u64 t, %1; cvt.u32.u64 %0, t; }"
        : "=r"(a) : "l"(p));
    return a;
}

__device__ __forceinline__ uint32_t packh2(float lo, float hi)
{
    uint32_t d;
    asm("cvt.rn.f16x2.f32 %0, %1, %2;" : "=r"(d) : "f"(hi), "f"(lo));
    return d;
}

#define CP_ASYNC16(dst, src) \
    asm volatile("cp.async.cg.shared.global [%0], [%1], 16;" :: "r"(dst), "l"(src) : "memory")
#define CP_COMMIT()  asm volatile("cp.async.commit_group;" ::: "memory")
#define CP_WAIT1()   asm volatile("cp.async.wait_group 1;" ::: "memory")

__device__ __forceinline__ void mma_f16(float (&d)[4],
                                        const uint32_t (&a)[4],
                                        const uint32_t (&b)[2])
{
    asm volatile(
        "mma.sync.aligned.m16n8k16.row.col.f32.f16.f16.f32 "
        "{%0,%1,%2,%3}, {%4,%5,%6,%7}, {%8,%9}, {%0,%1,%2,%3};\n"
        : "+f"(d[0]), "+f"(d[1]), "+f"(d[2]), "+f"(d[3])
        : "r"(a[0]), "r"(a[1]), "r"(a[2]), "r"(a[3]),
          "r"(b[0]), "r"(b[1]));
}

// ---------------- grouped GEMM (fp16 mma.sync + cp.async 3-stage) -----------
// G2=false (GEMM1 fused): B rows interleave w13 gate/up; epilogue does SwiGLU
//   and writes fp16 act (k-permuted). y-block covers 64 act columns.
// G2=true  (GEMM2, split-K): z-block sums K/KSPLIT slab into its own partial.
template<int KDIM, bool G2>
__global__ void __launch_bounds__(256, 2)
moe_gemm_h(const float* __restrict__ Bsrc)
{
    const int tile = blockIdx.x;
    if (tile >= g_ntiles) return;
    const int e        = g_tile_expert[tile];
    const int rowstart = g_tile_rowstart[tile];
    const int rowcnt   = g_tile_rowcnt[tile];
    const int nbase    = blockIdx.y * (G2 ? BN : 64);
    const int KLOC     = G2 ? KDIM / KSPLIT : KDIM;
    const int kbase    = G2 ? blockIdx.z * KLOC : 0;

    extern __shared__ uint32_t dsm[];
    const uint32_t smbase = smem_u32(dsm);
    const uint32_t base   = (smbase + 127u) & ~127u;
    char* dynb            = (char*)dsm + (base - smbase);

    const int tid  = threadIdx.x;
    const int lane = tid & 31;
    const int warp = tid >> 5;
    const int wm   = (warp & 1) * 64;
    const int wn   = (warp >> 1) * 32;
    const int g    = lane >> 2;
    const int tig  = lane & 3;

    // --- staging plans --------------------------------------------------------
    const __half* Ah   = G2 ? g_act_h : g_hidden_h;
    const int     NTOT = G2 ? HDIM : N1;
    const float*  Bexp = Bsrc + (size_t)e * NTOT * KDIM;

    // A: 128 rows x 64B (32 fp16) = 512 chunks of 16B -> 2 per thread
    const __half* aSrc[2]; uint32_t aOffDst[2];
#pragma unroll
    for (int i = 0; i < 2; i++) {
        int slot = tid + 256 * i;
        int row = slot >> 2, grp = slot & 3;
        int re = row < rowcnt ? row : rowcnt - 1;
        size_t srow = G2 ? (size_t)(rowstart + re)
                         : (size_t)g_row_token[rowstart + re];
        aSrc[i]    = Ah + srow * KDIM + kbase + grp * 8;
        aOffDst[i] = (uint32_t)(row * (BKPA * 2) + grp * 16);
    }
    // B: 128 rows x 128B = 1024 chunks -> 4 per thread
    const float* bSrc[4]; uint32_t bOffDst[4];
#pragma unroll
    for (int i = 0; i < 4; i++) {
        int slot = tid + 256 * i;
        int row = slot >> 3, grp = slot & 7;
        int srcrow = G2 ? (nbase + row)
                        : ((row & 1) ? IDIM : 0) + nbase + (row >> 1);
        bSrc[i]    = Bexp + (size_t)srcrow * KDIM + kbase + grp * 4;
        bOffDst[i] = (uint32_t)(ASTAGE + row * (BKPB * 4) + grp * 16);
    }

    float acc[4][4][4];
#pragma unroll
    for (int mt = 0; mt < 4; mt++)
#pragma unroll
        for (int nt = 0; nt < 4; nt++)
#pragma unroll
            for (int i = 0; i < 4; i++) acc[mt][nt][i] = 0.f;

    const int KITER = KLOC / BK;

    // --- prologue: issue stages 0,1 ------------------------------------------
#pragma unroll
    for (int s = 0; s < 2; s++) {
        const uint32_t sb = base + s * STAGE_BYTES;
#pragma unroll
        for (int i = 0; i < 2; i++)
            CP_ASYNC16(sb + aOffDst[i], aSrc[i] + s * BK);
#pragma unroll
        for (int i = 0; i < 4; i++)
            CP_ASYNC16(sb + bOffDst[i], bSrc[i] + s * BK);
        CP_COMMIT();
    }
    CP_WAIT1();
    __syncthreads();

    // fragment base offsets (within stage)
    const uint32_t aFB = (uint32_t)((wm + g) * (BKPA * 2) + tig * 8);
    const uint32_t bFB = (uint32_t)(ASTAGE + (wn + g) * (BKPB * 4) + tig * 8);

    int buf = 0, nxt = 2;
    for (int kt = 0; kt < KITER; kt++) {
        if (kt + 2 < KITER) {
            const uint32_t sb = base + nxt * STAGE_BYTES;
#pragma unroll
            for (int i = 0; i < 2; i++)
                CP_ASYNC16(sb + aOffDst[i], aSrc[i] + (kt + 2) * BK);
#pragma unroll
            for (int i = 0; i < 4; i++)
                CP_ASYNC16(sb + bOffDst[i], bSrc[i] + (kt + 2) * BK);
        }
        CP_COMMIT();

        char* sbuf = dynb + buf * STAGE_BYTES;
#pragma unroll
        for (int ks = 0; ks < 2; ks++) {
            uint32_t af[4][4], bf[4][2];
            const char* ab = sbuf + aFB + ks * 32;   // k16 group = 32B fp16
            const char* bb = sbuf + bFB + ks * 64;   // k16 group = 64B f32
#pragma unroll
            for (int mt = 0; mt < 4; mt++) {
                const char* p = ab + mt * (16 * BKPA * 2);
                uint2 lo = *(const uint2*)(p);                      // row g
                uint2 hi = *(const uint2*)(p + 8 * BKPA * 2);       // row g+8
                af[mt][0] = lo.x;
                af[mt][1] = hi.x;
                af[mt][2] = lo.y;
                af[mt][3] = hi.y;
            }
#pragma unroll
            for (int nt = 0; nt < 4; nt++) {
                const char* p = bb + nt * (8 * BKPB * 4);
                float2 lo = *(const float2*)(p);        // k = 2tig, 2tig+1
                float2 hi = *(const float2*)(p + 32);   // k = 2tig+8, 2tig+9
                bf[nt][0] = packh2(lo.x, lo.y);
                bf[nt][1] = packh2(hi.x, hi.y);
            }
#pragma unroll
            for (int mt = 0; mt < 4; mt++)
#pragma unroll
                for (int nt = 0; nt < 4; nt++)
                    mma_f16(acc[mt][nt], af[mt], bf[nt]);
        }

        CP_WAIT1();
        __syncthreads();
        buf = buf == NSTAGE - 1 ? 0 : buf + 1;
        nxt = nxt == NSTAGE - 1 ? 0 : nxt + 1;
    }

    // --- epilogue --------------------------------------------------------------
#pragma unroll
    for (int mt = 0; mt < 4; mt++) {
        int r0 = wm + mt * 16 + g;
#pragma unroll
        for (int half = 0; half < 2; half++) {
            int r = r0 + half * 8;
            if (r < rowcnt) {
                int gr = rowstart + r;
                if (G2) {
                    size_t cbase = (size_t)blockIdx.z * ((size_t)NROWS * HDIM)
                                 + (size_t)g_row_slot[gr] * HDIM + nbase;
                    float  wgt   = g_row_weight[gr];
#pragma unroll
                    for (int nt = 0; nt < 4; nt++) {
                        int c = wn + nt * 8 + 2 * tig;
                        float2 v;
                        v.x = acc[mt][nt][half * 2 + 0] * wgt;
                        v.y = acc[mt][nt][half * 2 + 1] * wgt;
                        *(float2*)&g_partial[cbase + c] = v;
                    }
                } else {
                    // fused SwiGLU: even col = gate, odd col = up of act col
                    size_t rb = (size_t)gr * IDIM;
#pragma unroll
                    for (int nt = 0; nt < 4; nt++) {
                        float x = acc[mt][nt][half * 2 + 0];
                        float u = acc[mt][nt][half * 2 + 1];
                        float a = (x / (1.f + __expf(-x))) * u;
                        int aj = nbase + (wn >> 1) + nt * 4 + tig;  // global act col
                        int p  = (aj >> 1) & 7;
                        int pj = (aj & ~15) + pslot(p) * 2 + (aj & 1);
                        g_act_h[rb + pj] = __float2half_rn(a);
                    }
                }
            }
        }
    }
}

// ---------------- combine (atomic-free, deterministic) ----------------------
__global__ void combine_kernel(float* __restrict__ out)
{
    size_t idx = (size_t)blockIdx.x * blockDim.x + threadIdx.x;   // T*H
    size_t t = idx / HDIM;
    const size_t SP = (size_t)NROWS * HDIM;
    size_t b0 = idx + t * HDIM;          // slot 2t
    float s = g_partial[b0] + g_partial[b0 + HDIM]
            + g_partial[SP + b0] + g_partial[SP + b0 + HDIM];
    out[idx] = s;
}

// ---------------- launch -----------------------------------------------------
extern "C" void kernel_launch(void* const* d_in, const int* in_sizes, int n_in,
                              void* d_out, int out_size)
{
    const float* hidden = (const float*)d_in[0];
    const int*   ids    = (const int*)d_in[1];
    const float* wts    = (const float*)d_in[2];
    // d_in[3] = router_logits (unused)
    const float* w13    = (const float*)d_in[4];
    const float* w2     = (const float*)d_in[5];
    float* out = (float*)d_out;

    const int smem_bytes = 128 + NSTAGE * STAGE_BYTES;   // 98432
    cudaFuncSetAttribute(moe_gemm_h<HDIM, false>,
                         cudaFuncAttributeMaxDynamicSharedMemorySize, smem_bytes);
    cudaFuncSetAttribute(moe_gemm_h<IDIM, true>,
                         cudaFuncAttributeMaxDynamicSharedMemorySize, smem_bytes);

    route_kernel<<<1, 256>>>(ids, wts);
    hconv_kernel<<<(TDIM * HDIM / 2) / 256, 256>>>(hidden);

    // GEMM1 (fused SwiGLU): each y-block produces 64 act columns
    moe_gemm_h<HDIM, false>
        <<<dim3(MAXTILES, IDIM / 64), 256, smem_bytes>>>(w13);

    // GEMM2: split-K=2 over z for wave balance
    moe_gemm_h<IDIM, true>
        <<<dim3(MAXTILES, HDIM / BN, KSPLIT), 256, smem_bytes>>>(w2);

    combine_kernel<<<(int)(((size_t)TDIM * HDIM) / 256), 256>>>(out);
}

// round 8
// speedup vs baseline: 2.5428x; 1.1420x over previous
#include <cuda_runtime.h>
#include <cuda_fp16.h>
#include <cstdint>

#define TDIM 1024
#define HDIM 2048
#define IDIM 5632
#define NEXP 8
#define TOPK 2
#define NROWS (TDIM * TOPK)       // 2048 routed rows
#define N1 (2 * IDIM)             // 11264 (gate+up)
#define BM 128
#define BN 128
#define BK 32
#define BKPB 40                   // B row stride (f32 elems) = 160B: conflict-free LDS.64
#define NSTAGE 3
#define MAXTILES 24
#define KSPLIT 2                  // GEMM2 split-K factor

#define ASTAGE 8192                         // interleaved A block: 128 rows x 32 fp16
#define BSTAGE (BN * BKPB * 4)              // 20480 B
#define STAGE_BYTES (ASTAGE + BSTAGE)       // 28672 B

// ---------------- scratch (device globals: no allocations allowed) ----------
__device__ int    g_row_token[NROWS];
__device__ float  g_row_weight[NROWS];
__device__ int    g_row_slot[NROWS];
__device__ int    g_tile_expert[MAXTILES];
__device__ int    g_tile_rowstart[MAXTILES];
__device__ int    g_tile_rowcnt[MAXTILES];
__device__ int    g_ntiles;
// tile-padded, M-interleaved, k-permuted fp16 A buffers
__device__ __half g_ax[(size_t)MAXTILES * 128 * HDIM];        // 12.6 MB (hidden per tile)
__device__ __half g_act_h[(size_t)MAXTILES * 128 * IDIM];     // 34.6 MB (activations)
__device__ float  g_partial[(size_t)KSPLIT * NROWS * HDIM];   // 32 MB

// interleaved offset (bytes) of element (local row r, k within 32-wide kt block)
// 16B chunk = { (rp,pA), (rp+8,pA), (rp,pB), (rp+8,pB) }, pB = pA+4 (k-pairs)
__device__ __forceinline__ uint32_t ilv_off(int r, int kin)
{
    int ks = kin >> 4, kk = kin & 15, p = kk >> 1;
    return (uint32_t)(ks * 4096 + (r >> 4) * 512 + (r & 7) * 64
         + (p & 3) * 16 + ((p >> 2) * 2 + ((r >> 3) & 1)) * 4 + (kk & 1) * 2);
}

// ---------------- routing ---------------------------------------------------
__global__ void route_kernel(const int* __restrict__ ids, const float* __restrict__ w)
{
    __shared__ int cnt[NEXP];
    __shared__ int off[NEXP];
    __shared__ int cur[NEXP];
    int tid = threadIdx.x;
    if (tid < NEXP) cnt[tid] = 0;
    __syncthreads();
    for (int a = tid; a < NROWS; a += blockDim.x)
        atomicAdd(&cnt[ids[a]], 1);
    __syncthreads();
    if (tid == 0) {
        int s = 0;
        for (int e = 0; e < NEXP; e++) { off[e] = s; cur[e] = s; s += cnt[e]; }
        int nt = 0;
        for (int e = 0; e < NEXP; e++) {
            for (int r = 0; r < cnt[e]; r += BM) {
                g_tile_expert[nt]   = e;
                g_tile_rowstart[nt] = off[e] + r;
                g_tile_rowcnt[nt]   = min(BM, cnt[e] - r);
                nt++;
            }
        }
        g_ntiles = nt;
    }
    __syncthreads();
    for (int a = tid; a < NROWS; a += blockDim.x) {
        int e = ids[a];
        int pos = atomicAdd(&cur[e], 1);
        g_row_token[pos]  = a / TOPK;
        g_row_weight[pos] = w[a];
        g_row_slot[pos]   = a;      // t*TOPK + k
    }
}

// ---------------- gather hidden -> tile-padded interleaved fp16 -------------
// block = (tile, local row r); 256 threads cover HDIM/2 = 1024 pairs (4 each)
__global__ void gather_kernel(const float* __restrict__ src)
{
    const int tile = blockIdx.x;
    if (tile >= g_ntiles) return;
    const int r      = blockIdx.y;
    const int rowcnt = g_tile_rowcnt[tile];
    const int re     = r < rowcnt ? r : rowcnt - 1;     // clamp padded rows
    const int token  = g_row_token[g_tile_rowstart[tile] + re];
    const float* srow = src + (size_t)token * HDIM;
    char* dbase = (char*)g_ax + (size_t)tile * (128 * HDIM * 2);
    const int tid = threadIdx.x;
#pragma unroll
    for (int j = 0; j < 4; j++) {
        int pg  = tid + j * 256;            // global pair index 0..1023
        int k16 = pg >> 3, p = pg & 7;
        float2 v = *(const float2*)(srow + k16 * 16 + p * 2);
        uint32_t off = (uint32_t)((k16 >> 1) * 8192 + (k16 & 1) * 4096
                     + (r >> 4) * 512 + (r & 7) * 64
                     + (p & 3) * 16 + ((p >> 2) * 2 + ((r >> 3) & 1)) * 4);
        *(__half2*)(dbase + off) = __floats2half2_rn(v.x, v.y);
    }
}

// ---------------- helpers ----------------------------------------------------
__device__ __forceinline__ uint32_t smem_u32(const void* p)
{
    uint32_t a;
    asm("{ .reg .u64 t; cvta.to.shared.u64 t, %1; cvt.u32.u64 %0, t; }"
        : "=r"(a) : "l"(p));
    return a;
}

__device__ __forceinline__ uint32_t packh2(float lo, float hi)
{
    uint32_t d;
    asm("cvt.rn.f16x2.f32 %0, %1, %2;" : "=r"(d) : "f"(hi), "f"(lo));
    return d;
}

#define CP_ASYNC16(dst, src) \
    asm volatile("cp.async.cg.shared.global [%0], [%1], 16;" :: "r"(dst), "l"(src) : "memory")
#define CP_COMMIT()  asm volatile("cp.async.commit_group;" ::: "memory")
#define CP_WAIT1()   asm volatile("cp.async.wait_group 1;" ::: "memory")

__device__ __forceinline__ void mma_f16(float (&d)[4],
                                        const uint32_t (&a)[4],
                                        const uint32_t (&b)[2])
{
    asm volatile(
        "mma.sync.aligned.m16n8k16.row.col.f32.f16.f16.f32 "
        "{%0,%1,%2,%3}, {%4,%5,%6,%7}, {%8,%9}, {%0,%1,%2,%3};\n"
        : "+f"(d[0]), "+f"(d[1]), "+f"(d[2]), "+f"(d[3])
        : "r"(a[0]), "r"(a[1]), "r"(a[2]), "r"(a[3]),
          "r"(b[0]), "r"(b[1]));
}

// ---------------- grouped GEMM (fp16 mma.sync + cp.async 3-stage) -----------
// A: interleaved fp16 blocks (one contiguous 8KB block copy per kt, LDS.128 frags)
// G2=false (GEMM1 fused SwiGLU): B rows interleave w13 gate/up; writes act.
// G2=true  (GEMM2, split-K): z-block sums K/KSPLIT slab into its own partial.
template<int KDIM, bool G2>
__global__ void __launch_bounds__(256, 2)
moe_gemm_h(const float* __restrict__ Bsrc)
{
    const int tile = blockIdx.x;
    if (tile >= g_ntiles) return;
    const int e        = g_tile_expert[tile];
    const int rowstart = g_tile_rowstart[tile];
    const int rowcnt   = g_tile_rowcnt[tile];
    const int nbase    = blockIdx.y * (G2 ? BN : 64);
    const int KLOC     = G2 ? KDIM / KSPLIT : KDIM;
    const int kbase    = G2 ? blockIdx.z * KLOC : 0;

    extern __shared__ uint32_t dsm[];
    const uint32_t smbase = smem_u32(dsm);
    const uint32_t base   = (smbase + 127u) & ~127u;
    char* dynb            = (char*)dsm + (base - smbase);

    const int tid  = threadIdx.x;
    const int lane = tid & 31;
    const int warp = tid >> 5;
    const int wm   = (warp & 1) * 64;
    const int wn   = (warp >> 1) * 32;
    const int g    = lane >> 2;
    const int tig  = lane & 3;

    // --- staging plans --------------------------------------------------------
    const char* aBase = (G2 ? (const char*)g_act_h : (const char*)g_ax)
                      + (size_t)tile * (128 * (size_t)KDIM * 2)
                      + (size_t)kbase * 256;           // kbase/32 blocks * 8192 B
    const int     NTOT = G2 ? HDIM : N1;
    const float*  Bexp = Bsrc + (size_t)e * NTOT * KDIM;

    // B: 128 rows x 128B = 1024 chunks -> 4 per thread
    const float* bSrc[4]; uint32_t bOffDst[4];
#pragma unroll
    for (int i = 0; i < 4; i++) {
        int slot = tid + 256 * i;
        int row = slot >> 3, grp = slot & 7;
        int srcrow = G2 ? (nbase + row)
                        : ((row & 1) ? IDIM : 0) + nbase + (row >> 1);
        bSrc[i]    = Bexp + (size_t)srcrow * KDIM + kbase + grp * 4;
        bOffDst[i] = (uint32_t)(ASTAGE + row * (BKPB * 4) + grp * 16);
    }
    const uint32_t aDst0 = (uint32_t)(tid * 16);
    const uint32_t aDst1 = (uint32_t)(4096 + tid * 16);

    float acc[4][4][4];
#pragma unroll
    for (int mt = 0; mt < 4; mt++)
#pragma unroll
        for (int nt = 0; nt < 4; nt++)
#pragma unroll
            for (int i = 0; i < 4; i++) acc[mt][nt][i] = 0.f;

    const int KITER = KLOC / BK;

    // --- prologue: issue stages 0,1 ------------------------------------------
#pragma unroll
    for (int s = 0; s < 2; s++) {
        const uint32_t sb = base + s * STAGE_BYTES;
        CP_ASYNC16(sb + aDst0, aBase + s * 8192 + aDst0);
        CP_ASYNC16(sb + aDst1, aBase + s * 8192 + aDst1);
#pragma unroll
        for (int i = 0; i < 4; i++)
            CP_ASYNC16(sb + bOffDst[i], bSrc[i] + s * BK);
        CP_COMMIT();
    }
    CP_WAIT1();
    __syncthreads();

    // fragment base offsets (within stage)
    const uint32_t aFB = (uint32_t)((wm >> 4) * 512 + g * 64 + tig * 16);
    const uint32_t bFB = (uint32_t)(ASTAGE + (wn + g) * (BKPB * 4) + tig * 8);

    int buf = 0, nxt = 2;
    for (int kt = 0; kt < KITER; kt++) {
        if (kt + 2 < KITER) {
            const uint32_t sb = base + nxt * STAGE_BYTES;
            CP_ASYNC16(sb + aDst0, aBase + (size_t)(kt + 2) * 8192 + aDst0);
            CP_ASYNC16(sb + aDst1, aBase + (size_t)(kt + 2) * 8192 + aDst1);
#pragma unroll
            for (int i = 0; i < 4; i++)
                CP_ASYNC16(sb + bOffDst[i], bSrc[i] + (kt + 2) * BK);
        }
        CP_COMMIT();

        char* sbuf = dynb + buf * STAGE_BYTES;
#pragma unroll
        for (int ks = 0; ks < 2; ks++) {
            uint32_t af[4][4], bf[4][2];
            const char* ab = sbuf + aFB + ks * 4096;
            const char* bb = sbuf + bFB + ks * 64;   // k16 group = 64B f32
#pragma unroll
            for (int mt = 0; mt < 4; mt++) {
                uint4 v = *(const uint4*)(ab + mt * 512);
                af[mt][0] = v.x;   // (g,   k 2tig..2tig+1)
                af[mt][1] = v.y;   // (g+8, k 2tig..2tig+1)
                af[mt][2] = v.z;   // (g,   k 2tig+8..2tig+9)
                af[mt][3] = v.w;   // (g+8, k 2tig+8..2tig+9)
            }
#pragma unroll
            for (int nt = 0; nt < 4; nt++) {
                const char* p = bb + nt * (8 * BKPB * 4);
                float2 lo = *(const float2*)(p);        // k = 2tig, 2tig+1
                float2 hi = *(const float2*)(p + 32);   // k = 2tig+8, 2tig+9
                bf[nt][0] = packh2(lo.x, lo.y);
                bf[nt][1] = packh2(hi.x, hi.y);
            }
#pragma unroll
            for (int mt = 0; mt < 4; mt++)
#pragma unroll
                for (int nt = 0; nt < 4; nt++)
                    mma_f16(acc[mt][nt], af[mt], bf[nt]);
        }

        CP_WAIT1();
        __syncthreads();
        buf = buf == NSTAGE - 1 ? 0 : buf + 1;
        nxt = nxt == NSTAGE - 1 ? 0 : nxt + 1;
    }

    // --- epilogue --------------------------------------------------------------
    char* actTile = (char*)g_act_h + (size_t)tile * (128 * (size_t)IDIM * 2);
#pragma unroll
    for (int mt = 0; mt < 4; mt++) {
        int r0 = wm + mt * 16 + g;
#pragma unroll
        for (int half = 0; half < 2; half++) {
            int r = r0 + half * 8;
            if (r < rowcnt) {
                int gr = rowstart + r;
                if (G2) {
                    size_t cbase = (size_t)blockIdx.z * ((size_t)NROWS * HDIM)
                                 + (size_t)g_row_slot[gr] * HDIM + nbase;
                    float  wgt   = g_row_weight[gr];
#pragma unroll
                    for (int nt = 0; nt < 4; nt++) {
                        int c = wn + nt * 8 + 2 * tig;
                        float2 v;
                        v.x = acc[mt][nt][half * 2 + 0] * wgt;
                        v.y = acc[mt][nt][half * 2 + 1] * wgt;
                        *(float2*)&g_partial[cbase + c] = v;
                    }
                } else {
                    // fused SwiGLU -> act in interleaved tile-padded layout
#pragma unroll
                    for (int nt = 0; nt < 4; nt++) {
                        float x = acc[mt][nt][half * 2 + 0];
                        float u = acc[mt][nt][half * 2 + 1];
                        float a = (x / (1.f + __expf(-x))) * u;
                        int aj = nbase + (wn >> 1) + nt * 4 + tig;   // act col
                        uint32_t off = (uint32_t)((aj >> 5) * 8192)
                                     + ilv_off(r, aj & 31);
                        *(__half*)(actTile + off) = __float2half_rn(a);
                    }
                }
            }
        }
    }
}

// ---------------- combine (atomic-free, deterministic) ----------------------
__global__ void combine_kernel(float* __restrict__ out)
{
    size_t idx = (size_t)blockIdx.x * blockDim.x + threadIdx.x;   // T*H
    size_t t = idx / HDIM;
    const size_t SP = (size_t)NROWS * HDIM;
    size_t b0 = idx + t * HDIM;          // slot 2t
    float s = g_partial[b0] + g_partial[b0 + HDIM]
            + g_partial[SP + b0] + g_partial[SP + b0 + HDIM];
    out[idx] = s;
}

// ---------------- launch -----------------------------------------------------
extern "C" void kernel_launch(void* const* d_in, const int* in_sizes, int n_in,
                              void* d_out, int out_size)
{
    const float* hidden = (const float*)d_in[0];
    const int*   ids    = (const int*)d_in[1];
    const float* wts    = (const float*)d_in[2];
    // d_in[3] = router_logits (unused)
    const float* w13    = (const float*)d_in[4];
    const float* w2     = (const float*)d_in[5];
    float* out = (float*)d_out;

    const int smem_bytes = 128 + NSTAGE * STAGE_BYTES;   // 86144
    cudaFuncSetAttribute(moe_gemm_h<HDIM, false>,
                         cudaFuncAttributeMaxDynamicSharedMemorySize, smem_bytes);
    cudaFuncSetAttribute(moe_gemm_h<IDIM, true>,
                         cudaFuncAttributeMaxDynamicSharedMemorySize, smem_bytes);

    route_kernel<<<1, 256>>>(ids, wts);
    gather_kernel<<<dim3(MAXTILES, 128), 256>>>(hidden);

    // GEMM1 (fused SwiGLU): each y-block produces 64 act columns
    moe_gemm_h<HDIM, false>
        <<<dim3(MAXTILES, IDIM / 64), 256, smem_bytes>>>(w13);

    // GEMM2: split-K=2 over z for wave balance
    moe_gemm_h<IDIM, true>
        <<<dim3(MAXTILES, HDIM / BN, KSPLIT), 256, smem_bytes>>>(w2);

    combine_kernel<<<(int)(((size_t)TDIM * HDIM) / 256), 256>>>(out);
}